// round 15
// baseline (speedup 1.0000x reference)
#include <cuda_runtime.h>
#include <cuda_fp16.h>
#include <cstdint>

// ---------------------------------------------------------------------------
// LongTermMemory: combined-weight pipeline with graph-capture stream fork.
//   s0: prep_a(x->fp16, W1^T) -> g1 (h=relu(x@W1+b1)) ----\
//   s1: prep_b(Wq/k/v^T, W2 fp16, bias fold) -> wcomb -----+-> qkv -> swa
// wcomb: WCt_s = Wst @ W2n (3 x 1024x1024x1024), so q/k/v = h @ WCt^T + bc.
// GEMM mainloop: proven R10 (BK=32, 3-stage cp.async, reg-double-buffered
// fragments, 2x4 warps, 2 CTA/SM) — at the mma.sync issue wall.
// ---------------------------------------------------------------------------

constexpr int M_TOT = 4096;
constexpr int DIMC  = 1024;
constexpr int SEQ   = 2048;
constexpr size_t WSZ = (size_t)DIMC * DIMC;

// ---------------- scratch ----------------
__device__ __half g_xh[M_TOT * DIMC];
__device__ __half g_h[M_TOT * DIMC];
__device__ __half g_qkvh[3][M_TOT * DIMC];
__device__ float g_bqkv[3 * DIMC];
__device__ __half g_w[5][DIMC * DIMC];   // 0=W1t, 2=Wqt, 3=Wkt, 4=Wvt
__device__ __half g_w2n[DIMC * DIMC];    // W2 plain fp16 [j][d]
__device__ __half g_wc[3][DIMC * DIMC];  // combined transposed weights [n][j]

// ---------------------------------------------------------------------------
// helpers
// ---------------------------------------------------------------------------
__device__ __forceinline__ uint32_t smem_u32(const void* p) {
    uint32_t a;
    asm("{ .reg .u64 t; cvta.to.shared.u64 t, %1; cvt.u32.u64 %0, t; }"
        : "=r"(a) : "l"(p));
    return a;
}
__device__ __forceinline__ void cp_async16(uint32_t saddr, const void* gaddr) {
    asm volatile("cp.async.cg.shared.global [%0], [%1], 16;"
                 :: "r"(saddr), "l"(gaddr));
}
#define CP_COMMIT()  asm volatile("cp.async.commit_group;" ::: "memory")
#define CP_WAIT(N)   asm volatile("cp.async.wait_group %0;" :: "n"(N) : "memory")

__device__ __forceinline__ void ldmatrix_x4(uint32_t& r0, uint32_t& r1,
                                            uint32_t& r2, uint32_t& r3,
                                            uint32_t addr) {
    asm volatile("ldmatrix.sync.aligned.m8n8.x4.shared.b16 {%0,%1,%2,%3}, [%4];"
                 : "=r"(r0), "=r"(r1), "=r"(r2), "=r"(r3) : "r"(addr));
}
__device__ __forceinline__ void ldmatrix_x2(uint32_t& r0, uint32_t& r1,
                                            uint32_t addr) {
    asm volatile("ldmatrix.sync.aligned.m8n8.x2.shared.b16 {%0,%1}, [%2];"
                 : "=r"(r0), "=r"(r1) : "r"(addr));
}
__device__ __forceinline__ void ldmatrix_x4_trans(uint32_t& r0, uint32_t& r1,
                                                  uint32_t& r2, uint32_t& r3,
                                                  uint32_t addr) {
    asm volatile("ldmatrix.sync.aligned.m8n8.x4.trans.shared.b16 {%0,%1,%2,%3}, [%4];"
                 : "=r"(r0), "=r"(r1), "=r"(r2), "=r"(r3) : "r"(addr));
}

__device__ __forceinline__ void mma16816(float* d, const uint32_t* a,
                                         uint32_t b0, uint32_t b1) {
    asm volatile(
        "mma.sync.aligned.m16n8k16.row.col.f32.f16.f16.f32 "
        "{%0,%1,%2,%3}, {%4,%5,%6,%7}, {%8,%9}, {%0,%1,%2,%3};"
        : "+f"(d[0]), "+f"(d[1]), "+f"(d[2]), "+f"(d[3])
        : "r"(a[0]), "r"(a[1]), "r"(a[2]), "r"(a[3]), "r"(b0), "r"(b1));
}

__device__ __forceinline__ void transpose_tile(const float* __restrict__ W,
                                               __half* __restrict__ out,
                                               int n0, int k0, int tid) {
    __shared__ float t[32][33];
    const int lane = tid & 31, r = tid >> 5;
    #pragma unroll
    for (int j = 0; j < 4; j++)
        t[r + 8 * j][lane] = W[(size_t)(k0 + r + 8 * j) * DIMC + n0 + lane];
    __syncthreads();
    const int n = tid >> 3;
    const int kb2 = (tid & 7) << 2;
    __half h0 = __float2half_rn(t[kb2 + 0][n]);
    __half h1 = __float2half_rn(t[kb2 + 1][n]);
    __half h2 = __float2half_rn(t[kb2 + 2][n]);
    __half h3 = __float2half_rn(t[kb2 + 3][n]);
    __half2 p0 = __halves2half2(h0, h1);
    __half2 p1 = __halves2half2(h2, h3);
    uint2 pk = make_uint2(*(uint32_t*)&p0, *(uint32_t*)&p1);
    *(uint2*)(out + (size_t)(n0 + n) * DIMC + k0 + kb2) = pk;
}

// ---------------------------------------------------------------------------
// prep_a (s0): x->fp16 (1024 blocks) + W1 transpose (1024 blocks)
// ---------------------------------------------------------------------------
__global__ __launch_bounds__(256)
void prep_a_kernel(const float* __restrict__ x, const float* __restrict__ w1,
                   __half* __restrict__ xh, __half* __restrict__ wt)
{
    const int b = blockIdx.x;
    const int tid = threadIdx.x;
    if (b < 1024) {
        const int i0 = b * 256 + tid;
        #pragma unroll
        for (int c = 0; c < 4; c++) {
            const int i = i0 + c * 262144;
            float4 v = ((const float4*)x)[i];
            __half2* hp = (__half2*)xh + 2 * i;
            hp[0] = __floats2half2_rn(v.x, v.y);
            hp[1] = __floats2half2_rn(v.z, v.w);
        }
    } else {
        const int within = b - 1024;
        const int n0 = (within & 31) << 5;
        const int k0 = (within >> 5) << 5;
        transpose_tile(w1, wt, n0, k0, tid);
    }
}

// ---------------------------------------------------------------------------
// prep_b (s1): Wq/Wk/Wv transposes (3072) + W2 fp16 (256) + bias fold (12)
// ---------------------------------------------------------------------------
__global__ __launch_bounds__(256)
void prep_b_kernel(const float* __restrict__ qw, const float* __restrict__ kw,
                   const float* __restrict__ vw, const float* __restrict__ w2,
                   const float* __restrict__ b2,
                   const float* __restrict__ qb, const float* __restrict__ kb,
                   const float* __restrict__ vb,
                   __half* __restrict__ wt, __half* __restrict__ w2n,
                   float* __restrict__ bqkv)
{
    const int b = blockIdx.x;
    const int tid = threadIdx.x;
    if (b < 3072) {
        const int wi = b >> 10;                    // 0..2
        const int within = b & 1023;
        const int n0 = (within & 31) << 5;
        const int k0 = (within >> 5) << 5;
        const float* W = (wi == 0) ? qw : (wi == 1) ? kw : vw;
        transpose_tile(W, wt + (size_t)(2 + wi) * WSZ, n0, k0, tid);
    } else if (b < 3328) {
        const int i0 = (b - 3072) * 256 + tid;
        #pragma unroll
        for (int c = 0; c < 4; c++) {
            const int i = i0 + c * 65536;
            float4 v = ((const float4*)w2)[i];
            __half2* hp = (__half2*)w2n + 2 * i;
            hp[0] = __floats2half2_rn(v.x, v.y);
            hp[1] = __floats2half2_rn(v.z, v.w);
        }
    } else {
        // bias fold: bc[n] = sum_d b2[d]*W[d][n] + b[n]   (coalesced rows)
        const int idx = b - 3328;                  // 0..11
        const int wsel = idx >> 2;
        const int n = ((idx & 3) << 8) + tid;
        const float* W = (wsel == 0) ? qw : (wsel == 1) ? kw : vw;
        const float* bb = (wsel == 0) ? qb : (wsel == 1) ? kb : vb;
        float acc = 0.0f;
        for (int d = 0; d < DIMC; d++)
            acc = fmaf(b2[d], W[(size_t)d * DIMC + n], acc);
        bqkv[wsel * DIMC + n] = acc + bb[n];
    }
}

// ---------------------------------------------------------------------------
// GEMM config (proven R10 mainloop)
// ---------------------------------------------------------------------------
constexpr int BK = 32;
constexpr int STRIDE = 40;
constexpr int TILE_E = 128 * STRIDE;
constexpr int TILE_B = TILE_E * 2;
constexpr int STAGE_B = 2 * TILE_B;
constexpr int GEMM_SMEM = 3 * STAGE_B;   // 61440 B

#define GEMM_BODY(A_row_base, B_row_base)                                     \
    const int lrow = tid >> 1;                                                \
    const int lsel = (tid & 1) * 16;                                          \
    const __half* gA = (A_row_base) + (size_t)lrow * DIMC + lsel;             \
    const __half* gB = (B_row_base) + (size_t)lrow * DIMC + lsel;             \
    const uint32_t sofs = (lrow * STRIDE + lsel) * 2;                         \
    auto load_stage = [&](int bufi, int kt) {                                 \
        const uint32_t s0a = sb + bufi * STAGE_B + sofs;                      \
        const int go = kt * BK;                                               \
        cp_async16(s0a,               gA + go);                               \
        cp_async16(s0a + 16,          gA + go + 8);                           \
        cp_async16(s0a + TILE_B,      gB + go);                               \
        cp_async16(s0a + TILE_B + 16, gB + go + 8);                           \
    };                                                                        \
    const int lr15 = lane & 15;                                               \
    const int lk8  = (lane >> 4) << 3;                                        \
    const uint32_t aBase = ((uint32_t)(wr * 64 + lr15) * STRIDE + lk8) * 2;   \
    const uint32_t bBase = ((uint32_t)(wc * 32 + lr15) * STRIDE + lk8) * 2 + TILE_B; \
    uint32_t ahf[2][4][4], bff[2][2][4];                                      \
    auto ld_frags = [&](int slot, uint32_t st, int s) {                       \
        const uint32_t kc = (uint32_t)(s * 16) * 2;                           \
        _Pragma("unroll")                                                     \
        for (int i = 0; i < 4; i++) {                                         \
            const uint32_t ro = st + aBase + (uint32_t)(i * 16 * STRIDE) * 2 + kc; \
            ldmatrix_x4(ahf[slot][i][0], ahf[slot][i][1],                     \
                        ahf[slot][i][2], ahf[slot][i][3], ro);                \
        }                                                                     \
        _Pragma("unroll")                                                     \
        for (int jj = 0; jj < 2; jj++) {                                      \
            const uint32_t ro = st + bBase + (uint32_t)(jj * 16 * STRIDE) * 2 + kc; \
            ldmatrix_x4(bff[slot][jj][0], bff[slot][jj][1],                   \
                        bff[slot][jj][2], bff[slot][jj][3], ro);              \
        }                                                                     \
    };                                                                        \
    float acc[4][4][4];                                                       \
    _Pragma("unroll")                                                         \
    for (int i = 0; i < 4; i++)                                               \
        _Pragma("unroll")                                                     \
        for (int j = 0; j < 4; j++)                                           \
            _Pragma("unroll")                                                 \
            for (int r = 0; r < 4; r++) acc[i][j][r] = 0.0f;                  \
    auto do_mma = [&](int slot) {                                             \
        _Pragma("unroll")                                                     \
        for (int i = 0; i < 4; i++)                                           \
            _Pragma("unroll")                                                 \
            for (int j = 0; j < 4; j++) {                                     \
                const int jj = j >> 1, sel = j & 1;                           \
                mma16816(acc[i][j], ahf[slot][i],                             \
                         bff[slot][jj][sel], bff[slot][jj][sel + 2]);         \
            }                                                                 \
    };                                                                        \
    load_stage(0, 0); CP_COMMIT();                                            \
    load_stage(1, 1); CP_COMMIT();                                            \
    CP_WAIT(1);                                                               \
    __syncthreads();                                                          \
    constexpr int NKT = DIMC / BK;                                            \
    int buf = 0;                                                              \
    ld_frags(0, sb, 0);                                                       \
    for (int kt = 0; kt < NKT; kt++) {                                        \
        const uint32_t st = sb + buf * STAGE_B;                               \
        ld_frags(1, st, 1);                                                   \
        if (kt + 2 < NKT) {                                                   \
            int nb = buf + 2; if (nb >= 3) nb -= 3;                           \
            load_stage(nb, kt + 2);                                           \
        }                                                                     \
        CP_COMMIT();                                                          \
        do_mma(0);                                                            \
        if (kt + 1 < NKT) {                                                   \
            CP_WAIT(1);                                                       \
            __syncthreads();                                                  \
            int nb = buf + 1; if (nb == 3) nb = 0;                            \
            ld_frags(0, sb + nb * STAGE_B, 0);                                \
            buf = nb;                                                         \
        }                                                                     \
        do_mma(1);                                                            \
    }

// g1: h = relu(x@W1 + b1), fp16 out. grid (8, 32).
__global__ __launch_bounds__(256, 2)
void gemm_g1_kernel(const __half* __restrict__ xh, const __half* __restrict__ w1t,
                    const float* __restrict__ b1, __half* __restrict__ h_out)
{
    extern __shared__ __half sm[];
    const uint32_t sb = smem_u32(sm);
    const int tid = threadIdx.x, wid = tid >> 5, lane = tid & 31;
    const int bx = blockIdx.x, by = blockIdx.y;
    const int wr = wid >> 2, wc = wid & 3;
    const int g = lane >> 2, tig = lane & 3;

    GEMM_BODY(xh + (size_t)by * 128 * DIMC, w1t + (size_t)bx * 128 * DIMC)

    #pragma unroll
    for (int i = 0; i < 4; i++) {
        const int mg0 = by * 128 + wr * 64 + i * 16 + g;
        #pragma unroll
        for (int j = 0; j < 4; j++) {
            const int ng = bx * 128 + wc * 32 + j * 8 + tig * 2;
            const float b0 = __ldg(b1 + ng);
            const float b1v = __ldg(b1 + ng + 1);
            float v00 = fmaxf(acc[i][j][0] + b0, 0.0f);
            float v01 = fmaxf(acc[i][j][1] + b1v, 0.0f);
            float v10 = fmaxf(acc[i][j][2] + b0, 0.0f);
            float v11 = fmaxf(acc[i][j][3] + b1v, 0.0f);
            const size_t o0 = (size_t)mg0 * DIMC + ng;
            const size_t o1 = (size_t)(mg0 + 8) * DIMC + ng;
            *(__half2*)(h_out + o0) = __floats2half2_rn(v00, v01);
            *(__half2*)(h_out + o1) = __floats2half2_rn(v10, v11);
        }
    }
}

// wcomb: wc_s = Wst @ W2n (no bias). grid (8, 24): wsel = by>>3, mtile = by&7.
__global__ __launch_bounds__(256, 2)
void gemm_wcomb_kernel(const __half* __restrict__ wt, const __half* __restrict__ w2n,
                       __half* __restrict__ wc_out)
{
    extern __shared__ __half sm[];
    const uint32_t sb = smem_u32(sm);
    const int tid = threadIdx.x, wid = tid >> 5, lane = tid & 31;
    const int bx = blockIdx.x;
    const int wsel = blockIdx.y >> 3;
    const int mtile = blockIdx.y & 7;
    const int wr = wid >> 2, wc = wid & 3;
    const int g = lane >> 2, tig = lane & 3;

    const __half* A = wt + (size_t)(2 + wsel) * WSZ + (size_t)mtile * 128 * DIMC;
    const __half* B = w2n + (size_t)bx * 128 * DIMC;
    __half* C = wc_out + (size_t)wsel * WSZ;

    GEMM_BODY(A, B)

    #pragma unroll
    for (int i = 0; i < 4; i++) {
        const int mg0 = mtile * 128 + wr * 64 + i * 16 + g;
        #pragma unroll
        for (int j = 0; j < 4; j++) {
            const int ng = bx * 128 + wc * 32 + j * 8 + tig * 2;
            const size_t o0 = (size_t)mg0 * DIMC + ng;
            const size_t o1 = (size_t)(mg0 + 8) * DIMC + ng;
            *(__half2*)(C + o0) = __floats2half2_rn(acc[i][j][0], acc[i][j][1]);
            *(__half2*)(C + o1) = __floats2half2_rn(acc[i][j][2], acc[i][j][3]);
        }
    }
}

// qkv: 3 stacked GEMMs from h with combined weights + folded bias, fp16 out.
// grid (24, 32): wsel = bx>>3.
__global__ __launch_bounds__(256, 2)
void gemm_qkv_kernel(const __half* __restrict__ h_in, const __half* __restrict__ wc_b,
                     const float* __restrict__ bias_b, __half* __restrict__ out_b)
{
    extern __shared__ __half sm[];
    const uint32_t sb = smem_u32(sm);
    const int tid = threadIdx.x, wid = tid >> 5, lane = tid & 31;
    int bx = blockIdx.x;
    const int by = blockIdx.y;
    const int wsel = bx >> 3; bx &= 7;
    const int wr = wid >> 2, wc = wid & 3;
    const int g = lane >> 2, tig = lane & 3;

    const __half* B = wc_b + (size_t)wsel * WSZ + (size_t)bx * 128 * DIMC;
    const float* bias = bias_b + wsel * DIMC;
    __half* C = out_b + (size_t)wsel * M_TOT * DIMC;

    GEMM_BODY(h_in + (size_t)by * 128 * DIMC, B)

    #pragma unroll
    for (int i = 0; i < 4; i++) {
        const int mg0 = by * 128 + wr * 64 + i * 16 + g;
        #pragma unroll
        for (int j = 0; j < 4; j++) {
            const int ng = bx * 128 + wc * 32 + j * 8 + tig * 2;
            const float b0 = __ldg(bias + ng);
            const float b1v = __ldg(bias + ng + 1);
            float v00 = acc[i][j][0] + b0;
            float v01 = acc[i][j][1] + b1v;
            float v10 = acc[i][j][2] + b0;
            float v11 = acc[i][j][3] + b1v;
            const size_t o0 = (size_t)mg0 * DIMC + ng;
            const size_t o1 = (size_t)(mg0 + 8) * DIMC + ng;
            *(__half2*)(C + o0) = __floats2half2_rn(v00, v01);
            *(__half2*)(C + o1) = __floats2half2_rn(v10, v11);
        }
    }
}

// ---------------------------------------------------------------------------
// Flash sliding-window attention v2 (R14: aliased smem, big d-chunks).
// ---------------------------------------------------------------------------
constexpr int QB = 32;
constexpr int BKD = 128;
constexpr int DC2 = 256;
constexpr int P1_STRIDE = 136;
constexpr int V_STRIDE  = 264;
constexpr int SF_STRIDE = 100;
constexpr int PS_STRIDE = 104;

constexpr int Q_ST1 = QB * P1_STRIDE * 2;
constexpr int K_ST1 = 96 * P1_STRIDE * 2;
constexpr int STG1  = Q_ST1 + K_ST1;
constexpr int V_ST2 = 96 * V_STRIDE * 2;
constexpr int OFF_S = 3 * STG1;
constexpr int OFF_P = OFF_S + QB * SF_STRIDE * 4;
constexpr int SWA_SMEM = OFF_P + QB * PS_STRIDE * 2;

__global__ __launch_bounds__(256, 1)
void swa_flash_kernel(const __half* __restrict__ q,
                      const __half* __restrict__ k,
                      const __half* __restrict__ v,
                      float* __restrict__ out)
{
    extern __shared__ char smc[];
    const uint32_t sb = smem_u32(smc);

    const int tid  = threadIdx.x;
    const int wid  = tid >> 5;
    const int lane = tid & 31;
    const int bid  = blockIdx.x;
    const int batch = bid >> 6;
    const int s0 = (bid & 63) * QB;

    const int wr = wid >> 2;
    const int wc = wid & 3;
    const int lr15 = lane & 15;
    const int lk8  = (lane >> 4) << 3;

    const size_t qbase = (size_t)(batch * SEQ + s0) * DIMC;
    const size_t kvbase = (size_t)batch * SEQ * DIMC;

    const int prow = tid >> 3;
    const int pcol = (tid & 7) * 16;
    auto load_qk = [&](int buf, int kt) {
        const int d0 = kt * BKD + pcol;
        const uint32_t qs = sb + buf * STG1 + (prow * P1_STRIDE + pcol) * 2;
        cp_async16(qs,      q + qbase + (size_t)prow * DIMC + d0);
        cp_async16(qs + 16, q + qbase + (size_t)prow * DIMC + d0 + 8);
        #pragma unroll
        for (int i = 0; i < 3; i++) {
            const int krow = prow + 32 * i;
            int jg = s0 - 32 + krow;
            jg = jg < 0 ? 0 : (jg >= SEQ ? SEQ - 1 : jg);
            const uint32_t ks = sb + buf * STG1 + Q_ST1 + (krow * P1_STRIDE + pcol) * 2;
            cp_async16(ks,      k + kvbase + (size_t)jg * DIMC + d0);
            cp_async16(ks + 16, k + kvbase + (size_t)jg * DIMC + d0 + 8);
        }
    };

    float accS[3][4];
    #pragma unroll
    for (int j = 0; j < 3; j++)
        #pragma unroll
        for (int r = 0; r < 4; r++) accS[j][r] = 0.0f;

    load_qk(0, 0); CP_COMMIT();
    load_qk(1, 1); CP_COMMIT();

    constexpr int NKT1 = DIMC / BKD;
    int buf = 0;
    for (int kt = 0; kt < NKT1; kt++) {
        CP_WAIT(1);
        __syncthreads();
        if (kt + 2 < NKT1) {
            int nb = buf + 2; if (nb >= 3) nb -= 3;
            load_qk(nb, kt + 2);
        }
        CP_COMMIT();

        const uint32_t sq = sb + buf * STG1;
        const uint32_t sk = sq + Q_ST1;

        #pragma unroll
        for (int ks = 0; ks < 8; ks++) {
            uint32_t a[4];
            ldmatrix_x4(a[0], a[1], a[2], a[3],
                        sq + ((uint32_t)(wr * 16 + lr15) * P1_STRIDE + ks * 16 + lk8) * 2);
            uint32_t br[3][2];
            #pragma unroll
            for (int gN = 0; gN < 3; gN++) {
                ldmatrix_x2(br[gN][0], br[gN][1],
                            sk + ((uint32_t)(wc * 24 + gN * 8 + (lane & 7)) * P1_STRIDE
                                  + ks * 16 + ((lane >> 3) & 1) * 8) * 2);
            }
            #pragma unroll
            for (int gN = 0; gN < 3; gN++)
                mma16816(accS[gN], a, br[gN][0], br[gN][1]);
        }
        if (++buf == 3) buf = 0;
    }

    {
        float* Sf = (float*)(smc + OFF_S);
        const int r0 = wr * 16 + (lane >> 2);
        const int c0 = wc * 24 + (lane & 3) * 2;
        #pragma unroll
        for (int gN = 0; gN < 3; gN++) {
            #pragma unroll
            for (int half = 0; half < 2; half++) {
                const int qi = r0 + half * 8;
                #pragma unroll
                for (int cc = 0; cc < 2; cc++) {
                    const int kj = c0 + gN * 8 + cc;
                    const int jg = s0 - 32 + kj;
                    const int d  = kj - qi;
                    const bool valid = (jg >= 0) && (jg < SEQ) && (d >= 0) && (d <= 64);
                    Sf[qi * SF_STRIDE + kj] =
                        valid ? accS[gN][half * 2 + cc] * 0.03125f : -1e30f;
                }
            }
        }
    }
    __syncthreads();

    {
        float* Sf = (float*)(smc + OFF_S);
        __half* Ps = (__half*)(smc + OFF_P);
        const int srow = tid >> 3;
        const int ssub = tid & 7;
        float vals[12];
        float mx = -1e30f;
        #pragma unroll
        for (int i = 0; i < 12; i++) {
            vals[i] = Sf[srow * SF_STRIDE + ssub * 12 + i];
            mx = fmaxf(mx, vals[i]);
        }
        #pragma unroll
        for (int off = 4; off; off >>= 1)
            mx = fmaxf(mx, __shfl_xor_sync(0xffffffffu, mx, off));
        float sum = 0.0f;
        #pragma unroll
        for (int i = 0; i < 12; i++) {
            vals[i] = __expf(vals[i] - mx);
            sum += vals[i];
        }
        #pragma unroll
        for (int off = 4; off; off >>= 1)
            sum += __shfl_xor_sync(0xffffffffu, sum, off);
        const float inv = 1.0f / sum;
        #pragma unroll
        for (int i = 0; i < 12; i++)
            Ps[srow * PS_STRIDE + ssub * 12 + i] = __float2half(vals[i] * inv);
    }
    CP_WAIT(0);
    __syncthreads();

    const int vrow = tid >> 4;
    const int vcol = (tid & 15) * 16;
    auto load_v = [&](int vbuf, int c) {
        const int d0 = c * DC2 + vcol;
        #pragma unroll
        for (int i = 0; i < 6; i++) {
            const int krow = vrow + 16 * i;
            int jg = s0 - 32 + krow;
            jg = jg < 0 ? 0 : (jg >= SEQ ? SEQ - 1 : jg);
            const uint32_t vs = sb + vbuf * V_ST2 + (krow * V_STRIDE + vcol) * 2;
            cp_async16(vs,      v + kvbase + (size_t)jg * DIMC + d0);
            cp_async16(vs + 16, v + kvbase + (size_t)jg * DIMC + d0 + 8);
        }
    };

    load_v(0, 0); CP_COMMIT();
    load_v(1, 1); CP_COMMIT();

    const uint32_t psb = sb + OFF_P;
    constexpr int NC = DIMC / DC2;
    for (int c = 0; c < NC; c++) {
        if (c + 1 < NC) { CP_WAIT(1); } else { CP_WAIT(0); }
        __syncthreads();

        const uint32_t sv = sb + (c & 1) * V_ST2;

        float acc2[8][4];
        #pragma unroll
        for (int j = 0; j < 8; j++)
            #pragma unroll
            for (int r = 0; r < 4; r++) acc2[j][r] = 0.0f;

        #pragma unroll
        for (int ks = 0; ks < 6; ks++) {
            uint32_t p[4];
            ldmatrix_x4(p[0], p[1], p[2], p[3],
                        psb + ((uint32_t)(wr * 16 + lr15) * PS_STRIDE + ks * 16 + lk8) * 2);
            uint32_t vbf[4][4];
            #pragma unroll
            for (int h = 0; h < 4; h++) {
                ldmatrix_x4_trans(vbf[h][0], vbf[h][1], vbf[h][2], vbf[h][3],
                                  sv + ((uint32_t)(ks * 16 + lr15) * V_STRIDE
                                        + wc * 64 + h * 16 + lk8) * 2);
            }
            #pragma unroll
            for (int j = 0; j < 8; j++)
                mma16816(acc2[j], p, vbf[j >> 1][(j & 1) * 2], vbf[j >> 1][(j & 1) * 2 + 1]);
        }

        __syncthreads();
        if (c + 2 < NC) {
            load_v(c & 1, c + 2);
        }
        CP_COMMIT();

        const int r0 = wr * 16 + (lane >> 2);
        #pragma unroll
        for (int j = 0; j < 8; j++) {
            const int col = c * DC2 + wc * 64 + j * 8 + (lane & 3) * 2;
            const size_t o0 = qbase + (size_t)r0 * DIMC + col;
            const size_t o1 = qbase + (size_t)(r0 + 8) * DIMC + col;
            *(float2*)(out + o0) = make_float2(acc2[j][0], acc2[j][1]);
            *(float2*)(out + o1) = make_float2(acc2[j][2], acc2[j][3]);
        }
    }
}

// ---------------------------------------------------------------------------
// launch with graph-capture stream fork:
//   s0: prep_a -> g1 ---------------\
//   s1: prep_b -> wcomb ------------+--> qkv -> swa
// ---------------------------------------------------------------------------
extern "C" void kernel_launch(void* const* d_in, const int* in_sizes, int n_in,
                              void* d_out, int out_size)
{
    const float* x     = (const float*)d_in[0];
    const float* nm_w1 = (const float*)d_in[1];
    const float* nm_b1 = (const float*)d_in[2];
    const float* nm_w2 = (const float*)d_in[3];
    const float* nm_b2 = (const float*)d_in[4];
    const float* q_w   = (const float*)d_in[5];
    const float* q_b   = (const float*)d_in[6];
    const float* k_w   = (const float*)d_in[7];
    const float* k_b   = (const float*)d_in[8];
    const float* v_w   = (const float*)d_in[9];
    const float* v_b   = (const float*)d_in[10];
    float* out = (float*)d_out;

    __half *xh, *h, *w, *w2n, *wcp, *qkvh;
    float *bqkv;
    cudaGetSymbolAddress((void**)&xh, g_xh);
    cudaGetSymbolAddress((void**)&h, g_h);
    cudaGetSymbolAddress((void**)&w, g_w);
    cudaGetSymbolAddress((void**)&w2n, g_w2n);
    cudaGetSymbolAddress((void**)&wcp, g_wc);
    cudaGetSymbolAddress((void**)&qkvh, g_qkvh);
    cudaGetSymbolAddress((void**)&bqkv, g_bqkv);

    cudaFuncSetAttribute(gemm_g1_kernel, cudaFuncAttributeMaxDynamicSharedMemorySize, GEMM_SMEM);
    cudaFuncSetAttribute(gemm_wcomb_kernel, cudaFuncAttributeMaxDynamicSharedMemorySize, GEMM_SMEM);
    cudaFuncSetAttribute(gemm_qkv_kernel, cudaFuncAttributeMaxDynamicSharedMemorySize, GEMM_SMEM);
    cudaFuncSetAttribute(swa_flash_kernel, cudaFuncAttributeMaxDynamicSharedMemorySize, SWA_SMEM);

    // fork stream + events (created per call; host code runs only on the
    // correctness + capture invocations, never during timed graph replays)
    cudaStream_t s1;
    cudaEvent_t evRoot, evJoin;
    cudaStreamCreateWithFlags(&s1, cudaStreamNonBlocking);
    cudaEventCreateWithFlags(&evRoot, cudaEventDisableTiming);
    cudaEventCreateWithFlags(&evJoin, cudaEventDisableTiming);

    // fork: s1 branch (independent of x)
    cudaEventRecord(evRoot, 0);
    cudaStreamWaitEvent(s1, evRoot, 0);
    prep_b_kernel<<<3072 + 256 + 12, 256, 0, s1>>>(q_w, k_w, v_w, nm_w2, nm_b2,
                                                   q_b, k_b, v_b, w, w2n, bqkv);
    gemm_wcomb_kernel<<<dim3(8, 24), 256, GEMM_SMEM, s1>>>(w, w2n, wcp);
    cudaEventRecord(evJoin, s1);

    // main branch
    prep_a_kernel<<<2048, 256>>>(x, nm_w1, xh, w);
    gemm_g1_kernel<<<dim3(8, 32), 256, GEMM_SMEM>>>(xh, w, nm_b1, h);

    // join, then qkv + attention
    cudaStreamWaitEvent(0, evJoin, 0);
    gemm_qkv_kernel<<<dim3(24, 32), 256, GEMM_SMEM>>>(h, wcp, bqkv, qkvh);

    const __half* qh = qkvh;
    const __half* kh = qkvh + (size_t)M_TOT * DIMC;
    const __half* vh = qkvh + 2 * (size_t)M_TOT * DIMC;
    swa_flash_kernel<<<128, 256, SWA_SMEM>>>(qh, kh, vh, out);
}

// round 16
// speedup vs baseline: 1.0881x; 1.0881x over previous
#include <cuda_runtime.h>
#include <cuda_fp16.h>
#include <cstdint>

// ---------------------------------------------------------------------------
// LongTermMemory — champion configuration (R10) restored:
// prep -> g1 -> g2 -> qkv(stacked x3) -> swa.
// GEMM: fp16 HMMA, BK=32, 3-stage cp.async, register-double-buffered
// fragments, 2x4 warps, 2 CTA/SM (~90% of the mma.sync issue ceiling;
// tcgen05 unavailable at compute_103). swa: flash-style 32q x 96k bands.
// Trims vs R10: prep-v2 (coalesced transpose stores, flat x convert),
// bias concat removed (qkv selects bias pointer per stack).
// ---------------------------------------------------------------------------

constexpr int M_TOT = 4096;
constexpr int DIMC  = 1024;
constexpr int SEQ   = 2048;
constexpr size_t WSZ = (size_t)DIMC * DIMC;

// ---------------- scratch ----------------
__device__ __half g_xh[M_TOT * DIMC];
__device__ __half g_h[M_TOT * DIMC];
__device__ __half g_m[M_TOT * DIMC];
__device__ __half g_qkvh[3][M_TOT * DIMC];
__device__ __half g_w[5][DIMC * DIMC];   // transposed: Wt[n][k], fp16

// ---------------------------------------------------------------------------
// helpers
// ---------------------------------------------------------------------------
__device__ __forceinline__ uint32_t smem_u32(const void* p) {
    uint32_t a;
    asm("{ .reg .u64 t; cvta.to.shared.u64 t, %1; cvt.u32.u64 %0, t; }"
        : "=r"(a) : "l"(p));
    return a;
}
__device__ __forceinline__ void cp_async16(uint32_t saddr, const void* gaddr) {
    asm volatile("cp.async.cg.shared.global [%0], [%1], 16;"
                 :: "r"(saddr), "l"(gaddr));
}
#define CP_COMMIT()  asm volatile("cp.async.commit_group;" ::: "memory")
#define CP_WAIT(N)   asm volatile("cp.async.wait_group %0;" :: "n"(N) : "memory")

__device__ __forceinline__ void ldmatrix_x4(uint32_t& r0, uint32_t& r1,
                                            uint32_t& r2, uint32_t& r3,
                                            uint32_t addr) {
    asm volatile("ldmatrix.sync.aligned.m8n8.x4.shared.b16 {%0,%1,%2,%3}, [%4];"
                 : "=r"(r0), "=r"(r1), "=r"(r2), "=r"(r3) : "r"(addr));
}
__device__ __forceinline__ void ldmatrix_x2(uint32_t& r0, uint32_t& r1,
                                            uint32_t addr) {
    asm volatile("ldmatrix.sync.aligned.m8n8.x2.shared.b16 {%0,%1}, [%2];"
                 : "=r"(r0), "=r"(r1) : "r"(addr));
}
__device__ __forceinline__ void ldmatrix_x4_trans(uint32_t& r0, uint32_t& r1,
                                                  uint32_t& r2, uint32_t& r3,
                                                  uint32_t addr) {
    asm volatile("ldmatrix.sync.aligned.m8n8.x4.trans.shared.b16 {%0,%1,%2,%3}, [%4];"
                 : "=r"(r0), "=r"(r1), "=r"(r2), "=r"(r3) : "r"(addr));
}

__device__ __forceinline__ void mma16816(float* d, const uint32_t* a,
                                         uint32_t b0, uint32_t b1) {
    asm volatile(
        "mma.sync.aligned.m16n8k16.row.col.f32.f16.f16.f32 "
        "{%0,%1,%2,%3}, {%4,%5,%6,%7}, {%8,%9}, {%0,%1,%2,%3};"
        : "+f"(d[0]), "+f"(d[1]), "+f"(d[2]), "+f"(d[3])
        : "r"(a[0]), "r"(a[1]), "r"(a[2]), "r"(a[3]), "r"(b0), "r"(b1));
}

// ---------------------------------------------------------------------------
// prep kernel (v2): x->fp16 flat (1024 blocks) + 5 transposes with packed
// 8B stores (5120 blocks).
// ---------------------------------------------------------------------------
__global__ __launch_bounds__(256)
void prep_kernel(const float* __restrict__ x,
                 const float* __restrict__ w1, const float* __restrict__ w2,
                 const float* __restrict__ qw, const float* __restrict__ kw,
                 const float* __restrict__ vw,
                 __half* __restrict__ xh, __half* __restrict__ wt)
{
    const int b = blockIdx.x;
    const int tid = threadIdx.x;
    if (b < 1024) {
        const int i0 = b * 256 + tid;
        #pragma unroll
        for (int c = 0; c < 4; c++) {
            const int i = i0 + c * 262144;
            float4 v = ((const float4*)x)[i];
            __half2* hp = (__half2*)xh + 2 * i;
            hp[0] = __floats2half2_rn(v.x, v.y);
            hp[1] = __floats2half2_rn(v.z, v.w);
        }
    } else {
        __shared__ float t[32][33];
        const int wb = b - 1024;
        const int wi = wb >> 10;
        const int within = wb & 1023;
        const int n0 = (within & 31) << 5;
        const int k0 = (within >> 5) << 5;
        const float* W = (wi == 0) ? w1 : (wi == 1) ? w2 :
                         (wi == 2) ? qw : (wi == 3) ? kw : vw;
        __half* out = wt + (size_t)wi * WSZ;
        const int lane = tid & 31, r = tid >> 5;
        #pragma unroll
        for (int j = 0; j < 4; j++)
            t[r + 8 * j][lane] = W[(size_t)(k0 + r + 8 * j) * DIMC + n0 + lane];
        __syncthreads();
        const int n = tid >> 3;
        const int kb2 = (tid & 7) << 2;
        __half h0 = __float2half_rn(t[kb2 + 0][n]);
        __half h1 = __float2half_rn(t[kb2 + 1][n]);
        __half h2 = __float2half_rn(t[kb2 + 2][n]);
        __half h3 = __float2half_rn(t[kb2 + 3][n]);
        __half2 p0 = __halves2half2(h0, h1);
        __half2 p1 = __halves2half2(h2, h3);
        uint2 pk = make_uint2(*(uint32_t*)&p0, *(uint32_t*)&p1);
        *(uint2*)(out + (size_t)(n0 + n) * DIMC + k0 + kb2) = pk;
    }
}

// ---------------------------------------------------------------------------
// HMMA GEMM (exact R10 mainloop): CTA 128x128, BK=32, 2x4 warps, 3-stage
// cp.async, register-double-buffered fragments, 2 CTAs/SM.
// NSTACK>1: grid.x = 8*NSTACK; B/bias/out selected by bx>>3 (bias from
// 3 separate pointers, no concat).
// ---------------------------------------------------------------------------
constexpr int BK = 32;
constexpr int STRIDE = 40;
constexpr int TILE_E = 128 * STRIDE;
constexpr int TILE_B = TILE_E * 2;
constexpr int STAGE_B = 2 * TILE_B;
constexpr int GEMM_SMEM = 3 * STAGE_B;   // 61440 B

template <int RELU, int NSTACK>
__global__ __launch_bounds__(256, 2)
void gemm_f16_kernel(const __half* __restrict__ A_h,
                     const __half* __restrict__ B_base,
                     const float* __restrict__ bias0,
                     const float* __restrict__ bias1,
                     const float* __restrict__ bias2,
                     __half* __restrict__ Ch_base)
{
    extern __shared__ __half sm[];
    const uint32_t sb = smem_u32(sm);

    const int tid  = threadIdx.x;
    const int wid  = tid >> 5;
    const int lane = tid & 31;
    int bx = blockIdx.x;
    const int by = blockIdx.y;
    int wsel = 0;
    if (NSTACK > 1) { wsel = bx >> 3; bx &= 7; }

    const __half* B   = B_base + (size_t)wsel * WSZ;
    const float* bias = (wsel == 0) ? bias0 : (wsel == 1) ? bias1 : bias2;
    __half* Ch = Ch_base + (size_t)wsel * M_TOT * DIMC;

    const int wr = wid >> 2;
    const int wc = wid & 3;
    const int g   = lane >> 2;
    const int tig = lane & 3;

    const int lrow = tid >> 1;
    const int lsel = (tid & 1) * 16;

    const __half* gA = A_h + (size_t)(by * 128 + lrow) * DIMC + lsel;
    const __half* gB = B   + (size_t)(bx * 128 + lrow) * DIMC + lsel;
    const uint32_t sofs = (lrow * STRIDE + lsel) * 2;

    auto load_stage = [&](int bufi, int kt) {
        const uint32_t s0 = sb + bufi * STAGE_B + sofs;
        const int go = kt * BK;
        cp_async16(s0,               gA + go);
        cp_async16(s0 + 16,          gA + go + 8);
        cp_async16(s0 + TILE_B,      gB + go);
        cp_async16(s0 + TILE_B + 16, gB + go + 8);
    };

    const int lr15 = lane & 15;
    const int lk8  = (lane >> 4) << 3;
    const uint32_t aBase = ((uint32_t)(wr * 64 + lr15) * STRIDE + lk8) * 2;
    const uint32_t bBase = ((uint32_t)(wc * 32 + lr15) * STRIDE + lk8) * 2 + TILE_B;

    uint32_t ahf[2][4][4], bff[2][2][4];

    auto ld_frags = [&](int slot, uint32_t st, int s) {
        const uint32_t kc = (uint32_t)(s * 16) * 2;
        #pragma unroll
        for (int i = 0; i < 4; i++) {
            const uint32_t ro = st + aBase + (uint32_t)(i * 16 * STRIDE) * 2 + kc;
            ldmatrix_x4(ahf[slot][i][0], ahf[slot][i][1],
                        ahf[slot][i][2], ahf[slot][i][3], ro);
        }
        #pragma unroll
        for (int jj = 0; jj < 2; jj++) {
            const uint32_t ro = st + bBase + (uint32_t)(jj * 16 * STRIDE) * 2 + kc;
            ldmatrix_x4(bff[slot][jj][0], bff[slot][jj][1],
                        bff[slot][jj][2], bff[slot][jj][3], ro);
        }
    };

    float acc[4][4][4];
    #pragma unroll
    for (int i = 0; i < 4; i++)
        #pragma unroll
        for (int j = 0; j < 4; j++)
            #pragma unroll
            for (int r = 0; r < 4; r++) acc[i][j][r] = 0.0f;

    auto do_mma = [&](int slot) {
        #pragma unroll
        for (int i = 0; i < 4; i++)
            #pragma unroll
            for (int j = 0; j < 4; j++) {
                const int jj = j >> 1, sel = j & 1;
                mma16816(acc[i][j], ahf[slot][i],
                         bff[slot][jj][sel], bff[slot][jj][sel + 2]);
            }
    };

    load_stage(0, 0); CP_COMMIT();
    load_stage(1, 1); CP_COMMIT();
    CP_WAIT(1);
    __syncthreads();

    constexpr int NKT = DIMC / BK;
    int buf = 0;
    ld_frags(0, sb, 0);

    for (int kt = 0; kt < NKT; kt++) {
        const uint32_t st = sb + buf * STAGE_B;
        ld_frags(1, st, 1);
        if (kt + 2 < NKT) {
            int nb = buf + 2; if (nb >= 3) nb -= 3;
            load_stage(nb, kt + 2);
        }
        CP_COMMIT();

        do_mma(0);

        if (kt + 1 < NKT) {
            CP_WAIT(1);
            __syncthreads();
            int nb = buf + 1; if (nb == 3) nb = 0;
            ld_frags(0, sb + nb * STAGE_B, 0);
            buf = nb;
        }

        do_mma(1);
    }

    #pragma unroll
    for (int i = 0; i < 4; i++) {
        const int mg0 = by * 128 + wr * 64 + i * 16 + g;
        #pragma unroll
        for (int j = 0; j < 4; j++) {
            const int ng = bx * 128 + wc * 32 + j * 8 + tig * 2;
            const float b0 = __ldg(bias + ng);
            const float b1 = __ldg(bias + ng + 1);
            float v00 = acc[i][j][0] + b0;
            float v01 = acc[i][j][1] + b1;
            float v10 = acc[i][j][2] + b0;
            float v11 = acc[i][j][3] + b1;
            if (RELU) {
                v00 = fmaxf(v00, 0.0f); v01 = fmaxf(v01, 0.0f);
                v10 = fmaxf(v10, 0.0f); v11 = fmaxf(v11, 0.0f);
            }
            const size_t o0 = (size_t)mg0 * DIMC + ng;
            const size_t o1 = (size_t)(mg0 + 8) * DIMC + ng;
            *(__half2*)(Ch + o0) = __floats2half2_rn(v00, v01);
            *(__half2*)(Ch + o1) = __floats2half2_rn(v10, v11);
        }
    }
}

// ---------------------------------------------------------------------------
// Flash-style sliding-window attention (exact R10/R7 version).
// ---------------------------------------------------------------------------
constexpr int QB = 32;
constexpr int KBAND = 96;
constexpr int BKD = 64;
constexpr int DC = 128;

constexpr int QS_STRIDE = 72;
constexpr int VS_STRIDE = 136;
constexpr int SF_STRIDE = 100;
constexpr int PS_STRIDE = 104;

constexpr int Q_ST = QB * QS_STRIDE * 2;
constexpr int K_ST = KBAND * QS_STRIDE * 2;
constexpr int V_ST = KBAND * VS_STRIDE * 2;
constexpr int OFF_Q = 0;
constexpr int OFF_K = OFF_Q + 3 * Q_ST;
constexpr int OFF_S = OFF_K + 3 * K_ST;
constexpr int OFF_P = OFF_S + QB * SF_STRIDE * 4;
constexpr int OFF_V = OFF_P + QB * PS_STRIDE * 2;
constexpr int SWA_SMEM = OFF_V + 3 * V_ST;

__global__ __launch_bounds__(256, 1)
void swa_flash_kernel(const __half* __restrict__ q,
                      const __half* __restrict__ k,
                      const __half* __restrict__ v,
                      float* __restrict__ out)
{
    extern __shared__ char smc[];
    const uint32_t sb = smem_u32(smc);

    const int tid  = threadIdx.x;
    const int wid  = tid >> 5;
    const int lane = tid & 31;
    const int bid  = blockIdx.x;
    const int batch = bid >> 6;
    const int s0 = (bid & 63) * QB;

    const int wr = wid >> 2;
    const int wc = wid & 3;
    const int lr15 = lane & 15;
    const int lk8  = (lane >> 4) << 3;

    const size_t qbase = (size_t)(batch * SEQ + s0) * DIMC;
    const size_t kvbase = (size_t)batch * SEQ * DIMC;

    const int qrow = tid >> 3;
    const int qch  = (tid & 7) * 8;
    auto load_qk = [&](int buf, int kt) {
        const int d0 = kt * BKD + qch;
        cp_async16(sb + OFF_Q + buf * Q_ST + (qrow * QS_STRIDE + qch) * 2,
                   q + qbase + (size_t)qrow * DIMC + d0);
        #pragma unroll
        for (int i = 0; i < 3; i++) {
            const int krow = qrow + 32 * i;
            int jg = s0 - 32 + krow;
            jg = jg < 0 ? 0 : (jg >= SEQ ? SEQ - 1 : jg);
            cp_async16(sb + OFF_K + buf * K_ST + (krow * QS_STRIDE + qch) * 2,
                       k + kvbase + (size_t)jg * DIMC + d0);
        }
    };

    float accS[3][4];
    #pragma unroll
    for (int j = 0; j < 3; j++)
        #pragma unroll
        for (int r = 0; r < 4; r++) accS[j][r] = 0.0f;

    load_qk(0, 0); CP_COMMIT();
    load_qk(1, 1); CP_COMMIT();

    constexpr int NKT1 = DIMC / BKD;
    int buf = 0;
    for (int kt = 0; kt < NKT1; kt++) {
        CP_WAIT(1);
        __syncthreads();
        if (kt + 2 < NKT1) {
            int nb = buf + 2; if (nb >= 3) nb -= 3;
            load_qk(nb, kt + 2);
        }
        CP_COMMIT();

        const uint32_t sq = sb + OFF_Q + buf * Q_ST;
        const uint32_t sk = sb + OFF_K + buf * K_ST;

        #pragma unroll
        for (int ks = 0; ks < 4; ks++) {
            uint32_t a[4];
            ldmatrix_x4(a[0], a[1], a[2], a[3],
                        sq + ((uint32_t)(wr * 16 + lr15) * QS_STRIDE + ks * 16 + lk8) * 2);
            uint32_t br[3][2];
            #pragma unroll
            for (int gN = 0; gN < 3; gN++) {
                ldmatrix_x2(br[gN][0], br[gN][1],
                            sk + ((uint32_t)(wc * 24 + gN * 8 + (lane & 7)) * QS_STRIDE
                                  + ks * 16 + ((lane >> 3) & 1) * 8) * 2);
            }
            #pragma unroll
            for (int gN = 0; gN < 3; gN++)
                mma16816(accS[gN], a, br[gN][0], br[gN][1]);
        }
        if (++buf == 3) buf = 0;
    }

    {
        float* Sf = (float*)(smc + OFF_S);
        const int r0 = wr * 16 + (lane >> 2);
        const int c0 = wc * 24 + (lane & 3) * 2;
        #pragma unroll
        for (int gN = 0; gN < 3; gN++) {
            #pragma unroll
            for (int half = 0; half < 2; half++) {
                const int qi = r0 + half * 8;
                #pragma unroll
                for (int cc = 0; cc < 2; cc++) {
                    const int kj = c0 + gN * 8 + cc;
                    const int jg = s0 - 32 + kj;
                    const int d  = kj - qi;
                    const bool valid = (jg >= 0) && (jg < SEQ) && (d >= 0) && (d <= 64);
                    Sf[qi * SF_STRIDE + kj] =
                        valid ? accS[gN][half * 2 + cc] * 0.03125f : -1e30f;
                }
            }
        }
    }
    __syncthreads();

    {
        float* Sf = (float*)(smc + OFF_S);
        __half* Ps = (__half*)(smc + OFF_P);
        const int srow = tid >> 3;
        const int ssub = tid & 7;
        float vals[12];
        float mx = -1e30f;
        #pragma unroll
        for (int i = 0; i < 12; i++) {
            vals[i] = Sf[srow * SF_STRIDE + ssub * 12 + i];
            mx = fmaxf(mx, vals[i]);
        }
        #pragma unroll
        for (int off = 4; off; off >>= 1)
            mx = fmaxf(mx, __shfl_xor_sync(0xffffffffu, mx, off));
        float sum = 0.0f;
        #pragma unroll
        for (int i = 0; i < 12; i++) {
            vals[i] = __expf(vals[i] - mx);
            sum += vals[i];
        }
        #pragma unroll
        for (int off = 4; off; off >>= 1)
            sum += __shfl_xor_sync(0xffffffffu, sum, off);
        const float inv = 1.0f / sum;
        #pragma unroll
        for (int i = 0; i < 12; i++)
            Ps[srow * PS_STRIDE + ssub * 12 + i] = __float2half(vals[i] * inv);
    }
    CP_WAIT(0);
    __syncthreads();

    const int vrow16 = tid >> 4;
    const int vch    = (tid & 15) * 8;
    auto load_v = [&](int vbuf, int c) {
        const int d0 = c * DC + vch;
        #pragma unroll
        for (int i = 0; i < 6; i++) {
            const int krow = vrow16 + 16 * i;
            int jg = s0 - 32 + krow;
            jg = jg < 0 ? 0 : (jg >= SEQ ? SEQ - 1 : jg);
            cp_async16(sb + OFF_V + vbuf * V_ST + (krow * VS_STRIDE + vch) * 2,
                       v + kvbase + (size_t)jg * DIMC + d0);
        }
    };

    load_v(0, 0); CP_COMMIT();
    load_v(1, 1); CP_COMMIT();

    const uint32_t psb = sb + OFF_P;
    int vb = 0;
    constexpr int NC = DIMC / DC;
    for (int c = 0; c < NC; c++) {
        CP_WAIT(1);
        __syncthreads();
        if (c + 2 < NC) {
            int nb = vb + 2; if (nb >= 3) nb -= 3;
            load_v(nb, c + 2);
        }
        CP_COMMIT();

        const uint32_t sv = sb + OFF_V + vb * V_ST;

        float acc2[4][4];
        #pragma unroll
        for (int j = 0; j < 4; j++)
            #pragma unroll
            for (int r = 0; r < 4; r++) acc2[j][r] = 0.0f;

        #pragma unroll
        for (int ks = 0; ks < 6; ks++) {
            uint32_t p[4];
            ldmatrix_x4(p[0], p[1], p[2], p[3],
                        psb + ((uint32_t)(wr * 16 + lr15) * PS_STRIDE + ks * 16 + lk8) * 2);
            uint32_t vbf[2][4];
            #pragma unroll
            for (int h = 0; h < 2; h++) {
                ldmatrix_x4_trans(vbf[h][0], vbf[h][1], vbf[h][2], vbf[h][3],
                                  sv + ((uint32_t)(ks * 16 + lr15) * VS_STRIDE
                                        + wc * 32 + h * 16 + lk8) * 2);
            }
            #pragma unroll
            for (int j = 0; j < 4; j++)
                mma16816(acc2[j], p, vbf[j >> 1][(j & 1) * 2], vbf[j >> 1][(j & 1) * 2 + 1]);
        }

        const int r0 = wr * 16 + (lane >> 2);
        #pragma unroll
        for (int j = 0; j < 4; j++) {
            const int col = c * DC + wc * 32 + j * 8 + (lane & 3) * 2;
            const size_t o0 = qbase + (size_t)r0 * DIMC + col;
            const size_t o1 = qbase + (size_t)(r0 + 8) * DIMC + col;
            *(float2*)(out + o0) = make_float2(acc2[j][0], acc2[j][1]);
            *(float2*)(out + o1) = make_float2(acc2[j][2], acc2[j][3]);
        }
        if (++vb == 3) vb = 0;
    }
}

// ---------------------------------------------------------------------------
// launch: prep -> g1 -> g2 -> qkv(stacked) -> swa
// ---------------------------------------------------------------------------
extern "C" void kernel_launch(void* const* d_in, const int* in_sizes, int n_in,
                              void* d_out, int out_size)
{
    const float* x     = (const float*)d_in[0];
    const float* nm_w1 = (const float*)d_in[1];
    const float* nm_b1 = (const float*)d_in[2];
    const float* nm_w2 = (const float*)d_in[3];
    const float* nm_b2 = (const float*)d_in[4];
    const float* q_w   = (const float*)d_in[5];
    const float* q_b   = (const float*)d_in[6];
    const float* k_w   = (const float*)d_in[7];
    const float* k_b   = (const float*)d_in[8];
    const float* v_w   = (const float*)d_in[9];
    const float* v_b   = (const float*)d_in[10];
    float* out = (float*)d_out;

    __half *xh, *h, *m, *w, *qkvh;
    cudaGetSymbolAddress((void**)&xh, g_xh);
    cudaGetSymbolAddress((void**)&h, g_h);
    cudaGetSymbolAddress((void**)&m, g_m);
    cudaGetSymbolAddress((void**)&w, g_w);
    cudaGetSymbolAddress((void**)&qkvh, g_qkvh);

    cudaFuncSetAttribute(gemm_f16_kernel<1,1>, cudaFuncAttributeMaxDynamicSharedMemorySize, GEMM_SMEM);
    cudaFuncSetAttribute(gemm_f16_kernel<0,1>, cudaFuncAttributeMaxDynamicSharedMemorySize, GEMM_SMEM);
    cudaFuncSetAttribute(gemm_f16_kernel<0,3>, cudaFuncAttributeMaxDynamicSharedMemorySize, GEMM_SMEM);
    cudaFuncSetAttribute(swa_flash_kernel, cudaFuncAttributeMaxDynamicSharedMemorySize, SWA_SMEM);

    prep_kernel<<<1024 + 5 * 1024, 256>>>(x, nm_w1, nm_w2, q_w, k_w, v_w, xh, w);

    dim3 grid(8, 32);
    gemm_f16_kernel<1,1><<<grid, 256, GEMM_SMEM>>>(xh, w + 0 * WSZ,
                                                   nm_b1, nm_b1, nm_b1, h);
    gemm_f16_kernel<0,1><<<grid, 256, GEMM_SMEM>>>(h,  w + 1 * WSZ,
                                                   nm_b2, nm_b2, nm_b2, m);

    dim3 gridQKV(24, 32);
    gemm_f16_kernel<0,3><<<gridQKV, 256, GEMM_SMEM>>>(m, w + 2 * WSZ,
                                                      q_b, k_b, v_b, qkvh);

    const __half* qh = qkvh;
    const __half* kh = qkvh + (size_t)M_TOT * DIMC;
    const __half* vh = qkvh + 2 * (size_t)M_TOT * DIMC;
    swa_flash_kernel<<<128, 256, SWA_SMEM>>>(qh, kh, vh, out);
}

// round 17
// speedup vs baseline: 1.1437x; 1.0511x over previous
#include <cuda_runtime.h>
#include <cuda_fp16.h>
#include <cstdint>

// ---------------------------------------------------------------------------
// LongTermMemory — R16 champion GEMM/swa, with g1+g2+qkv fused into ONE
// 1280-CTA launch using row-block readiness flags (decoupled dependencies):
//   bid [0,256):   g1  tile (by,bx): h = relu(x@W1+b1)      -> flag1[by]++
//   bid [256,512): g2  tile: waits flag1[by]==8, m = h@W2+b2 -> flag2[by]++
//   bid [512,1280): qkv tiles: wait flag2[by]==8
// Removes g1/g2 wave-imbalance idle (256 CTAs on 296 slots) by letting later
// stages fill the holes. GEMM mainloop: proven R10 (BK=32, 3-stage cp.async,
// reg-double-buffered frags, 2x4 warps, 2 CTA/SM — mma.sync issue wall).
// ---------------------------------------------------------------------------

constexpr int M_TOT = 4096;
constexpr int DIMC  = 1024;
constexpr int SEQ   = 2048;
constexpr size_t WSZ = (size_t)DIMC * DIMC;

// ---------------- scratch ----------------
__device__ __half g_xh[M_TOT * DIMC];
__device__ __half g_h[M_TOT * DIMC];
__device__ __half g_m[M_TOT * DIMC];
__device__ __half g_qkvh[3][M_TOT * DIMC];
__device__ __half g_w[5][DIMC * DIMC];   // transposed: Wt[n][k], fp16
__device__ int g_flag1[32];
__device__ int g_flag2[32];

// ---------------------------------------------------------------------------
// helpers
// ---------------------------------------------------------------------------
__device__ __forceinline__ uint32_t smem_u32(const void* p) {
    uint32_t a;
    asm("{ .reg .u64 t; cvta.to.shared.u64 t, %1; cvt.u32.u64 %0, t; }"
        : "=r"(a) : "l"(p));
    return a;
}
__device__ __forceinline__ void cp_async16(uint32_t saddr, const void* gaddr) {
    asm volatile("cp.async.cg.shared.global [%0], [%1], 16;"
                 :: "r"(saddr), "l"(gaddr));
}
#define CP_COMMIT()  asm volatile("cp.async.commit_group;" ::: "memory")
#define CP_WAIT(N)   asm volatile("cp.async.wait_group %0;" :: "n"(N) : "memory")

__device__ __forceinline__ void ldmatrix_x4(uint32_t& r0, uint32_t& r1,
                                            uint32_t& r2, uint32_t& r3,
                                            uint32_t addr) {
    asm volatile("ldmatrix.sync.aligned.m8n8.x4.shared.b16 {%0,%1,%2,%3}, [%4];"
                 : "=r"(r0), "=r"(r1), "=r"(r2), "=r"(r3) : "r"(addr));
}
__device__ __forceinline__ void ldmatrix_x2(uint32_t& r0, uint32_t& r1,
                                            uint32_t addr) {
    asm volatile("ldmatrix.sync.aligned.m8n8.x2.shared.b16 {%0,%1}, [%2];"
                 : "=r"(r0), "=r"(r1) : "r"(addr));
}
__device__ __forceinline__ void ldmatrix_x4_trans(uint32_t& r0, uint32_t& r1,
                                                  uint32_t& r2, uint32_t& r3,
                                                  uint32_t addr) {
    asm volatile("ldmatrix.sync.aligned.m8n8.x4.trans.shared.b16 {%0,%1,%2,%3}, [%4];"
                 : "=r"(r0), "=r"(r1), "=r"(r2), "=r"(r3) : "r"(addr));
}

__device__ __forceinline__ void mma16816(float* d, const uint32_t* a,
                                         uint32_t b0, uint32_t b1) {
    asm volatile(
        "mma.sync.aligned.m16n8k16.row.col.f32.f16.f16.f32 "
        "{%0,%1,%2,%3}, {%4,%5,%6,%7}, {%8,%9}, {%0,%1,%2,%3};"
        : "+f"(d[0]), "+f"(d[1]), "+f"(d[2]), "+f"(d[3])
        : "r"(a[0]), "r"(a[1]), "r"(a[2]), "r"(a[3]), "r"(b0), "r"(b1));
}

// ---------------------------------------------------------------------------
// prep kernel: x->fp16 flat (1024) + 5 transposes (5120) + flag reset (1).
// ---------------------------------------------------------------------------
__global__ __launch_bounds__(256)
void prep_kernel(const float* __restrict__ x,
                 const float* __restrict__ w1, const float* __restrict__ w2,
                 const float* __restrict__ qw, const float* __restrict__ kw,
                 const float* __restrict__ vw,
                 __half* __restrict__ xh, __half* __restrict__ wt)
{
    const int b = blockIdx.x;
    const int tid = threadIdx.x;
    if (b < 1024) {
        const int i0 = b * 256 + tid;
        #pragma unroll
        for (int c = 0; c < 4; c++) {
            const int i = i0 + c * 262144;
            float4 v = ((const float4*)x)[i];
            __half2* hp = (__half2*)xh + 2 * i;
            hp[0] = __floats2half2_rn(v.x, v.y);
            hp[1] = __floats2half2_rn(v.z, v.w);
        }
    } else if (b < 1024 + 5120) {
        __shared__ float t[32][33];
        const int wb = b - 1024;
        const int wi = wb >> 10;
        const int within = wb & 1023;
        const int n0 = (within & 31) << 5;
        const int k0 = (within >> 5) << 5;
        const float* W = (wi == 0) ? w1 : (wi == 1) ? w2 :
                         (wi == 2) ? qw : (wi == 3) ? kw : vw;
        __half* out = wt + (size_t)wi * WSZ;
        const int lane = tid & 31, r = tid >> 5;
        #pragma unroll
        for (int j = 0; j < 4; j++)
            t[r + 8 * j][lane] = W[(size_t)(k0 + r + 8 * j) * DIMC + n0 + lane];
        __syncthreads();
        const int n = tid >> 3;
        const int kb2 = (tid & 7) << 2;
        __half h0 = __float2half_rn(t[kb2 + 0][n]);
        __half h1 = __float2half_rn(t[kb2 + 1][n]);
        __half h2 = __float2half_rn(t[kb2 + 2][n]);
        __half h3 = __float2half_rn(t[kb2 + 3][n]);
        __half2 p0 = __halves2half2(h0, h1);
        __half2 p1 = __halves2half2(h2, h3);
        uint2 pk = make_uint2(*(uint32_t*)&p0, *(uint32_t*)&p1);
        *(uint2*)(out + (size_t)(n0 + n) * DIMC + k0 + kb2) = pk;
    } else {
        if (tid < 32) { g_flag1[tid] = 0; g_flag2[tid] = 0; }
    }
}

// ---------------------------------------------------------------------------
// Mega GEMM kernel: g1 + g2 + qkv in one launch with row-block flags.
// Exact R10 mainloop. 1280 CTAs, 256 thr, 2 CTA/SM.
// ---------------------------------------------------------------------------
constexpr int BK = 32;
constexpr int STRIDE = 40;
constexpr int TILE_E = 128 * STRIDE;
constexpr int TILE_B = TILE_E * 2;
constexpr int STAGE_B = 2 * TILE_B;
constexpr int GEMM_SMEM = 3 * STAGE_B;   // 61440 B

__global__ __launch_bounds__(256, 2)
void gemm_mega_kernel(const __half* __restrict__ xh,
                      const __half* __restrict__ wt,
                      const float* __restrict__ b1f,
                      const float* __restrict__ b2f,
                      const float* __restrict__ qb,
                      const float* __restrict__ kb,
                      const float* __restrict__ vb,
                      __half* __restrict__ h_out,
                      __half* __restrict__ m_out,
                      __half* __restrict__ qkv_out)
{
    extern __shared__ __half sm[];
    const uint32_t sb = smem_u32(sm);

    const int tid  = threadIdx.x;
    const int wid  = tid >> 5;
    const int lane = tid & 31;
    const int bid  = blockIdx.x;

    const __half* A;
    const __half* B;
    const float* bias;
    __half* C;
    int relu = 0, by, bx;
    volatile int* waitf = nullptr;
    int* postf = nullptr;

    if (bid < 256) {
        by = bid >> 3; bx = bid & 7;
        A = xh; B = wt; bias = b1f; C = h_out; relu = 1;
        postf = &g_flag1[by];
    } else if (bid < 512) {
        const int i = bid - 256;
        by = i >> 3; bx = i & 7;
        A = h_out; B = wt + WSZ; bias = b2f; C = m_out;
        waitf = (volatile int*)&g_flag1[by];
        postf = &g_flag2[by];
    } else {
        const int i = bid - 512;
        const int wsel = i >> 8;
        const int r = i & 255;
        by = r >> 3; bx = r & 7;
        A = m_out;
        B = wt + (size_t)(2 + wsel) * WSZ;
        bias = (wsel == 0) ? qb : (wsel == 1) ? kb : vb;
        C = qkv_out + (size_t)wsel * M_TOT * DIMC;
        waitf = (volatile int*)&g_flag2[by];
    }

    // dependency spin (thread 0 only), then acquire
    if (waitf) {
        if (tid == 0) {
            while (*waitf < 8) { }
        }
        __syncthreads();
        __threadfence();
    }

    const int wr = wid >> 2;
    const int wc = wid & 3;
    const int g   = lane >> 2;
    const int tig = lane & 3;

    const int lrow = tid >> 1;
    const int lsel = (tid & 1) * 16;

    const __half* gA = A + (size_t)(by * 128 + lrow) * DIMC + lsel;
    const __half* gB = B + (size_t)(bx * 128 + lrow) * DIMC + lsel;
    const uint32_t sofs = (lrow * STRIDE + lsel) * 2;

    auto load_stage = [&](int bufi, int kt) {
        const uint32_t s0 = sb + bufi * STAGE_B + sofs;
        const int go = kt * BK;
        cp_async16(s0,               gA + go);
        cp_async16(s0 + 16,          gA + go + 8);
        cp_async16(s0 + TILE_B,      gB + go);
        cp_async16(s0 + TILE_B + 16, gB + go + 8);
    };

    const int lr15 = lane & 15;
    const int lk8  = (lane >> 4) << 3;
    const uint32_t aBase = ((uint32_t)(wr * 64 + lr15) * STRIDE + lk8) * 2;
    const uint32_t bBase = ((uint32_t)(wc * 32 + lr15) * STRIDE + lk8) * 2 + TILE_B;

    uint32_t ahf[2][4][4], bff[2][2][4];

    auto ld_frags = [&](int slot, uint32_t st, int s) {
        const uint32_t kc = (uint32_t)(s * 16) * 2;
        #pragma unroll
        for (int i = 0; i < 4; i++) {
            const uint32_t ro = st + aBase + (uint32_t)(i * 16 * STRIDE) * 2 + kc;
            ldmatrix_x4(ahf[slot][i][0], ahf[slot][i][1],
                        ahf[slot][i][2], ahf[slot][i][3], ro);
        }
        #pragma unroll
        for (int jj = 0; jj < 2; jj++) {
            const uint32_t ro = st + bBase + (uint32_t)(jj * 16 * STRIDE) * 2 + kc;
            ldmatrix_x4(bff[slot][jj][0], bff[slot][jj][1],
                        bff[slot][jj][2], bff[slot][jj][3], ro);
        }
    };

    float acc[4][4][4];
    #pragma unroll
    for (int i = 0; i < 4; i++)
        #pragma unroll
        for (int j = 0; j < 4; j++)
            #pragma unroll
            for (int r = 0; r < 4; r++) acc[i][j][r] = 0.0f;

    auto do_mma = [&](int slot) {
        #pragma unroll
        for (int i = 0; i < 4; i++)
            #pragma unroll
            for (int j = 0; j < 4; j++) {
                const int jj = j >> 1, sel = j & 1;
                mma16816(acc[i][j], ahf[slot][i],
                         bff[slot][jj][sel], bff[slot][jj][sel + 2]);
            }
    };

    load_stage(0, 0); CP_COMMIT();
    load_stage(1, 1); CP_COMMIT();
    CP_WAIT(1);
    __syncthreads();

    constexpr int NKT = DIMC / BK;
    int buf = 0;
    ld_frags(0, sb, 0);

    for (int kt = 0; kt < NKT; kt++) {
        const uint32_t st = sb + buf * STAGE_B;
        ld_frags(1, st, 1);
        if (kt + 2 < NKT) {
            int nb = buf + 2; if (nb >= 3) nb -= 3;
            load_stage(nb, kt + 2);
        }
        CP_COMMIT();

        do_mma(0);

        if (kt + 1 < NKT) {
            CP_WAIT(1);
            __syncthreads();
            int nb = buf + 1; if (nb == 3) nb = 0;
            ld_frags(0, sb + nb * STAGE_B, 0);
            buf = nb;
        }

        do_mma(1);
    }

    #pragma unroll
    for (int i = 0; i < 4; i++) {
        const int mg0 = by * 128 + wr * 64 + i * 16 + g;
        #pragma unroll
        for (int j = 0; j < 4; j++) {
            const int ng = bx * 128 + wc * 32 + j * 8 + tig * 2;
            const float b0 = __ldg(bias + ng);
            const float b1v = __ldg(bias + ng + 1);
            float v00 = acc[i][j][0] + b0;
            float v01 = acc[i][j][1] + b1v;
            float v10 = acc[i][j][2] + b0;
            float v11 = acc[i][j][3] + b1v;
            if (relu) {
                v00 = fmaxf(v00, 0.0f); v01 = fmaxf(v01, 0.0f);
                v10 = fmaxf(v10, 0.0f); v11 = fmaxf(v11, 0.0f);
            }
            const size_t o0 = (size_t)mg0 * DIMC + ng;
            const size_t o1 = (size_t)(mg0 + 8) * DIMC + ng;
            *(__half2*)(C + o0) = __floats2half2_rn(v00, v01);
            *(__half2*)(C + o1) = __floats2half2_rn(v10, v11);
        }
    }

    // release: make tile visible, then bump flag
    if (postf) {
        __threadfence();
        __syncthreads();
        if (tid == 0) atomicAdd(postf, 1);
    }
}

// ---------------------------------------------------------------------------
// Flash-style sliding-window attention (exact R16 version).
// ---------------------------------------------------------------------------
constexpr int QB = 32;
constexpr int KBAND = 96;
constexpr int BKD = 64;
constexpr int DC = 128;

constexpr int QS_STRIDE = 72;
constexpr int VS_STRIDE = 136;
constexpr int SF_STRIDE = 100;
constexpr int PS_STRIDE = 104;

constexpr int Q_ST = QB * QS_STRIDE * 2;
constexpr int K_ST = KBAND * QS_STRIDE * 2;
constexpr int V_ST = KBAND * VS_STRIDE * 2;
constexpr int OFF_Q = 0;
constexpr int OFF_K = OFF_Q + 3 * Q_ST;
constexpr int OFF_S = OFF_K + 3 * K_ST;
constexpr int OFF_P = OFF_S + QB * SF_STRIDE * 4;
constexpr int OFF_V = OFF_P + QB * PS_STRIDE * 2;
constexpr int SWA_SMEM = OFF_V + 3 * V_ST;

__global__ __launch_bounds__(256, 1)
void swa_flash_kernel(const __half* __restrict__ q,
                      const __half* __restrict__ k,
                      const __half* __restrict__ v,
                      float* __restrict__ out)
{
    extern __shared__ char smc[];
    const uint32_t sb = smem_u32(smc);

    const int tid  = threadIdx.x;
    const int wid  = tid >> 5;
    const int lane = tid & 31;
    const int bid  = blockIdx.x;
    const int batch = bid >> 6;
    const int s0 = (bid & 63) * QB;

    const int wr = wid >> 2;
    const int wc = wid & 3;
    const int lr15 = lane & 15;
    const int lk8  = (lane >> 4) << 3;

    const size_t qbase = (size_t)(batch * SEQ + s0) * DIMC;
    const size_t kvbase = (size_t)batch * SEQ * DIMC;

    const int qrow = tid >> 3;
    const int qch  = (tid & 7) * 8;
    auto load_qk = [&](int buf, int kt) {
        const int d0 = kt * BKD + qch;
        cp_async16(sb + OFF_Q + buf * Q_ST + (qrow * QS_STRIDE + qch) * 2,
                   q + qbase + (size_t)qrow * DIMC + d0);
        #pragma unroll
        for (int i = 0; i < 3; i++) {
            const int krow = qrow + 32 * i;
            int jg = s0 - 32 + krow;
            jg = jg < 0 ? 0 : (jg >= SEQ ? SEQ - 1 : jg);
            cp_async16(sb + OFF_K + buf * K_ST + (krow * QS_STRIDE + qch) * 2,
                       k + kvbase + (size_t)jg * DIMC + d0);
        }
    };

    float accS[3][4];
    #pragma unroll
    for (int j = 0; j < 3; j++)
        #pragma unroll
        for (int r = 0; r < 4; r++) accS[j][r] = 0.0f;

    load_qk(0, 0); CP_COMMIT();
    load_qk(1, 1); CP_COMMIT();

    constexpr int NKT1 = DIMC / BKD;
    int buf = 0;
    for (int kt = 0; kt < NKT1; kt++) {
        CP_WAIT(1);
        __syncthreads();
        if (kt + 2 < NKT1) {
            int nb = buf + 2; if (nb >= 3) nb -= 3;
            load_qk(nb, kt + 2);
        }
        CP_COMMIT();

        const uint32_t sq = sb + OFF_Q + buf * Q_ST;
        const uint32_t sk = sb + OFF_K + buf * K_ST;

        #pragma unroll
        for (int ks = 0; ks < 4; ks++) {
            uint32_t a[4];
            ldmatrix_x4(a[0], a[1], a[2], a[3],
                        sq + ((uint32_t)(wr * 16 + lr15) * QS_STRIDE + ks * 16 + lk8) * 2);
            uint32_t br[3][2];
            #pragma unroll
            for (int gN = 0; gN < 3; gN++) {
                ldmatrix_x2(br[gN][0], br[gN][1],
                            sk + ((uint32_t)(wc * 24 + gN * 8 + (lane & 7)) * QS_STRIDE
                                  + ks * 16 + ((lane >> 3) & 1) * 8) * 2);
            }
            #pragma unroll
            for (int gN = 0; gN < 3; gN++)
                mma16816(accS[gN], a, br[gN][0], br[gN][1]);
        }
        if (++buf == 3) buf = 0;
    }

    {
        float* Sf = (float*)(smc + OFF_S);
        const int r0 = wr * 16 + (lane >> 2);
        const int c0 = wc * 24 + (lane & 3) * 2;
        #pragma unroll
        for (int gN = 0; gN < 3; gN++) {
            #pragma unroll
            for (int half = 0; half < 2; half++) {
                const int qi = r0 + half * 8;
                #pragma unroll
                for (int cc = 0; cc < 2; cc++) {
                    const int kj = c0 + gN * 8 + cc;
                    const int jg = s0 - 32 + kj;
                    const int d  = kj - qi;
                    const bool valid = (jg >= 0) && (jg < SEQ) && (d >= 0) && (d <= 64);
                    Sf[qi * SF_STRIDE + kj] =
                        valid ? accS[gN][half * 2 + cc] * 0.03125f : -1e30f;
                }
            }
        }
    }
    __syncthreads();

    {
        float* Sf = (float*)(smc + OFF_S);
        __half* Ps = (__half*)(smc + OFF_P);
        const int srow = tid >> 3;
        const int ssub = tid & 7;
        float vals[12];
        float mx = -1e30f;
        #pragma unroll
        for (int i = 0; i < 12; i++) {
            vals[i] = Sf[srow * SF_STRIDE + ssub * 12 + i];
            mx = fmaxf(mx, vals[i]);
        }
        #pragma unroll
        for (int off = 4; off; off >>= 1)
            mx = fmaxf(mx, __shfl_xor_sync(0xffffffffu, mx, off));
        float sum = 0.0f;
        #pragma unroll
        for (int i = 0; i < 12; i++) {
            vals[i] = __expf(vals[i] - mx);
            sum += vals[i];
        }
        #pragma unroll
        for (int off = 4; off; off >>= 1)
            sum += __shfl_xor_sync(0xffffffffu, sum, off);
        const float inv = 1.0f / sum;
        #pragma unroll
        for (int i = 0; i < 12; i++)
            Ps[srow * PS_STRIDE + ssub * 12 + i] = __float2half(vals[i] * inv);
    }
    CP_WAIT(0);
    __syncthreads();

    const int vrow16 = tid >> 4;
    const int vch    = (tid & 15) * 8;
    auto load_v = [&](int vbuf, int c) {
        const int d0 = c * DC + vch;
        #pragma unroll
        for (int i = 0; i < 6; i++) {
            const int krow = vrow16 + 16 * i;
            int jg = s0 - 32 + krow;
            jg = jg < 0 ? 0 : (jg >= SEQ ? SEQ - 1 : jg);
            cp_async16(sb + OFF_V + vbuf * V_ST + (krow * VS_STRIDE + vch) * 2,
                       v + kvbase + (size_t)jg * DIMC + d0);
        }
    };

    load_v(0, 0); CP_COMMIT();
    load_v(1, 1); CP_COMMIT();

    const uint32_t psb = sb + OFF_P;
    int vb = 0;
    constexpr int NC = DIMC / DC;
    for (int c = 0; c < NC; c++) {
        CP_WAIT(1);
        __syncthreads();
        if (c + 2 < NC) {
            int nb = vb + 2; if (nb >= 3) nb -= 3;
            load_v(nb, c + 2);
        }
        CP_COMMIT();

        const uint32_t sv = sb + OFF_V + vb * V_ST;

        float acc2[4][4];
        #pragma unroll
        for (int j = 0; j < 4; j++)
            #pragma unroll
            for (int r = 0; r < 4; r++) acc2[j][r] = 0.0f;

        #pragma unroll
        for (int ks = 0; ks < 6; ks++) {
            uint32_t p[4];
            ldmatrix_x4(p[0], p[1], p[2], p[3],
                        psb + ((uint32_t)(wr * 16 + lr15) * PS_STRIDE + ks * 16 + lk8) * 2);
            uint32_t vbf[2][4];
            #pragma unroll
            for (int h = 0; h < 2; h++) {
                ldmatrix_x4_trans(vbf[h][0], vbf[h][1], vbf[h][2], vbf[h][3],
                                  sv + ((uint32_t)(ks * 16 + lr15) * VS_STRIDE
                                        + wc * 32 + h * 16 + lk8) * 2);
            }
            #pragma unroll
            for (int j = 0; j < 4; j++)
                mma16816(acc2[j], p, vbf[j >> 1][(j & 1) * 2], vbf[j >> 1][(j & 1) * 2 + 1]);
        }

        const int r0 = wr * 16 + (lane >> 2);
        #pragma unroll
        for (int j = 0; j < 4; j++) {
            const int col = c * DC + wc * 32 + j * 8 + (lane & 3) * 2;
            const size_t o0 = qbase + (size_t)r0 * DIMC + col;
            const size_t o1 = qbase + (size_t)(r0 + 8) * DIMC + col;
            *(float2*)(out + o0) = make_float2(acc2[j][0], acc2[j][1]);
            *(float2*)(out + o1) = make_float2(acc2[j][2], acc2[j][3]);
        }
        if (++vb == 3) vb = 0;
    }
}

// ---------------------------------------------------------------------------
// launch: prep -> mega(g1+g2+qkv) -> swa   (3 launches)
// ---------------------------------------------------------------------------
extern "C" void kernel_launch(void* const* d_in, const int* in_sizes, int n_in,
                              void* d_out, int out_size)
{
    const float* x     = (const float*)d_in[0];
    const float* nm_w1 = (const float*)d_in[1];
    const float* nm_b1 = (const float*)d_in[2];
    const float* nm_w2 = (const float*)d_in[3];
    const float* nm_b2 = (const float*)d_in[4];
    const float* q_w   = (const float*)d_in[5];
    const float* q_b   = (const float*)d_in[6];
    const float* k_w   = (const float*)d_in[7];
    const float* k_b   = (const float*)d_in[8];
    const float* v_w   = (const float*)d_in[9];
    const float* v_b   = (const float*)d_in[10];
    float* out = (float*)d_out;

    __half *xh, *h, *m, *w, *qkvh;
    cudaGetSymbolAddress((void**)&xh, g_xh);
    cudaGetSymbolAddress((void**)&h, g_h);
    cudaGetSymbolAddress((void**)&m, g_m);
    cudaGetSymbolAddress((void**)&w, g_w);
    cudaGetSymbolAddress((void**)&qkvh, g_qkvh);

    cudaFuncSetAttribute(gemm_mega_kernel, cudaFuncAttributeMaxDynamicSharedMemorySize, GEMM_SMEM);
    cudaFuncSetAttribute(swa_flash_kernel, cudaFuncAttributeMaxDynamicSharedMemorySize, SWA_SMEM);

    // launch 1: conversions + transposes + flag reset
    prep_kernel<<<1024 + 5 * 1024 + 1, 256>>>(x, nm_w1, nm_w2, q_w, k_w, v_w, xh, w);

    // launch 2: fused g1 + g2 + qkv with row-block dependency flags
    gemm_mega_kernel<<<1280, 256, GEMM_SMEM>>>(xh, w, nm_b1, nm_b2,
                                               q_b, k_b, v_b, h, m, qkvh);

    // launch 3: attention
    const __half* qh = qkvh;
    const __half* kh = qkvh + (size_t)M_TOT * DIMC;
    const __half* vh = qkvh + 2 * (size_t)M_TOT * DIMC;
    swa_flash_kernel<<<128, 256, SWA_SMEM>>>(qh, kh, vh, out);
}